// round 1
// baseline (speedup 1.0000x reference)
#include <cuda_runtime.h>
#include <cuda_bf16.h>
#include <math.h>

#define BATCH 1024
#define MBUF  16384
#define DIM   512
#define NCLS  100
#define NLRN  50
#define NBINS 4096
#define CAND_MAX 4096

// ---------------- scratch (__device__ globals; no allocation) ----------------
__device__ __align__(16) __nv_bfloat16 g_fn16[BATCH * DIM];
__device__ __align__(16) float         g_fn32[BATCH * DIM];
__device__ __align__(16) __nv_bfloat16 g_bfn16[(size_t)MBUF * DIM];
__device__ unsigned char               g_blu8[MBUF];
__device__ __align__(16) float         g_sims[(size_t)BATCH * MBUF];
__device__ float g_scores[BATCH];
__device__ float g_row_loss[BATCH];
__device__ int   g_row_valid[BATCH];
__device__ float g_row_kl[BATCH];
__device__ float g_bl[NCLS];
__device__ int   g_vc[NCLS];
__device__ __align__(16) float g_op[NLRN * DIM];
__device__ __align__(16) float g_np[NLRN * DIM];

__device__ __forceinline__ float clip10(float x) { return fminf(fmaxf(x, -10.f), 10.f); }

// ---------------- K1a: normalize features, also scores = sigmoid(f.W+b) -----
__global__ void k_norm_features(const float* __restrict__ f,
                                const float* __restrict__ W,
                                const float* __restrict__ b) {
    int r = blockIdx.x, t = threadIdx.x;
    __shared__ float r1[128], r2[128];
    float ss = 0.f, dw = 0.f;
    for (int d = t; d < DIM; d += 128) {
        float v = f[r * DIM + d];
        ss += v * v;
        dw += v * W[d];
    }
    r1[t] = ss; r2[t] = dw; __syncthreads();
    for (int s = 64; s > 0; s >>= 1) {
        if (t < s) { r1[t] += r1[t + s]; r2[t] += r2[t + s]; }
        __syncthreads();
    }
    float inv = 1.f / fmaxf(sqrtf(r1[0]), 1e-12f);
    if (t == 0) g_scores[r] = 1.f / (1.f + expf(-(r2[0] + b[0])));
    for (int d = t; d < DIM; d += 128) {
        float v = f[r * DIM + d] * inv;
        g_fn32[r * DIM + d] = v;
        g_fn16[r * DIM + d] = __float2bfloat16(v);
    }
}

// ---------------- K1b: normalize buffer rows ---------------------------------
__global__ void k_norm_buffer(const float* __restrict__ bf,
                              const int* __restrict__ blab) {
    int r = blockIdx.x, t = threadIdx.x;
    __shared__ float r1[128];
    float ss = 0.f;
    for (int d = t; d < DIM; d += 128) {
        float v = bf[(size_t)r * DIM + d];
        ss += v * v;
    }
    r1[t] = ss; __syncthreads();
    for (int s = 64; s > 0; s >>= 1) {
        if (t < s) r1[t] += r1[t + s];
        __syncthreads();
    }
    float inv = 1.f / fmaxf(sqrtf(r1[0]), 1e-12f);
    for (int d = t; d < DIM; d += 128)
        g_bfn16[(size_t)r * DIM + d] = __float2bfloat16(bf[(size_t)r * DIM + d] * inv);
    if (t == 0) g_blu8[r] = (unsigned char)blab[r];
}

// ---------------- K2: bf16 tensor-core GEMM, sims = clip(5*A.B^T) ------------
// C[1024,16384] = A[1024,512] * B[16384,512]^T ; BM=BN=128, BK=32, 8 warps.
__global__ void __launch_bounds__(256) k_gemm() {
    __shared__ __nv_bfloat16 sA[2][128 * 40];  // row stride 40 bf16 (20 uints; conflict-free frag loads)
    __shared__ __nv_bfloat16 sB[2][128 * 40];
    const __nv_bfloat16* A  = g_fn16;
    const __nv_bfloat16* Bm = g_bfn16;
    int tid  = threadIdx.x;
    int wid  = tid >> 5, lane = tid & 31;
    int gid  = lane >> 2, qid = lane & 3;
    int bm   = blockIdx.y * 128, bn = blockIdx.x * 128;
    int wm   = (wid >> 2) * 64,  wn = (wid & 3) * 32;

    float acc[4][4][4];
#pragma unroll
    for (int i = 0; i < 4; i++)
#pragma unroll
        for (int j = 0; j < 4; j++)
#pragma unroll
            for (int q = 0; q < 4; q++) acc[i][j][q] = 0.f;

    int lr = tid >> 1, lc = (tid & 1) * 16;
    const __nv_bfloat16* Ap0 = A  + (size_t)(bm + lr) * DIM + lc;
    const __nv_bfloat16* Bp0 = Bm + (size_t)(bn + lr) * DIM + lc;
    int so = lr * 40 + lc;

    uint4 ra0 = *(const uint4*)Ap0, ra1 = *(const uint4*)(Ap0 + 8);
    uint4 rb0 = *(const uint4*)Bp0, rb1 = *(const uint4*)(Bp0 + 8);
    *(uint4*)&sA[0][so] = ra0; *(uint4*)&sA[0][so + 8] = ra1;
    *(uint4*)&sB[0][so] = rb0; *(uint4*)&sB[0][so + 8] = rb1;
    __syncthreads();

    int buf = 0;
#pragma unroll 1
    for (int kk = 0; kk < 16; kk++) {
        if (kk < 15) {
            const __nv_bfloat16* Ap = Ap0 + (kk + 1) * 32;
            const __nv_bfloat16* Bp = Bp0 + (kk + 1) * 32;
            ra0 = *(const uint4*)Ap; ra1 = *(const uint4*)(Ap + 8);
            rb0 = *(const uint4*)Bp; rb1 = *(const uint4*)(Bp + 8);
        }
        const unsigned* sAu = (const unsigned*)sA[buf];
        const unsigned* sBu = (const unsigned*)sB[buf];
#pragma unroll
        for (int s = 0; s < 2; s++) {
            unsigned afr[4][4], bfr[4][2];
#pragma unroll
            for (int mt = 0; mt < 4; mt++) {
                int rl = (wm + mt * 16 + gid) * 20 + s * 8;
                afr[mt][0] = sAu[rl + qid];
                afr[mt][1] = sAu[rl + 160 + qid];   // +8 rows
                afr[mt][2] = sAu[rl + 4 + qid];
                afr[mt][3] = sAu[rl + 164 + qid];
            }
#pragma unroll
            for (int nt = 0; nt < 4; nt++) {
                int rl = (wn + nt * 8 + gid) * 20 + s * 8;
                bfr[nt][0] = sBu[rl + qid];
                bfr[nt][1] = sBu[rl + 4 + qid];
            }
#pragma unroll
            for (int mt = 0; mt < 4; mt++)
#pragma unroll
                for (int nt = 0; nt < 4; nt++) {
                    asm volatile(
                        "mma.sync.aligned.m16n8k16.row.col.f32.bf16.bf16.f32 "
                        "{%0,%1,%2,%3}, {%4,%5,%6,%7}, {%8,%9}, {%0,%1,%2,%3};\n"
                        : "+f"(acc[mt][nt][0]), "+f"(acc[mt][nt][1]),
                          "+f"(acc[mt][nt][2]), "+f"(acc[mt][nt][3])
                        : "r"(afr[mt][0]), "r"(afr[mt][1]), "r"(afr[mt][2]), "r"(afr[mt][3]),
                          "r"(bfr[nt][0]), "r"(bfr[nt][1]));
                }
        }
        if (kk < 15) {
            int b2 = buf ^ 1;
            *(uint4*)&sA[b2][so] = ra0; *(uint4*)&sA[b2][so + 8] = ra1;
            *(uint4*)&sB[b2][so] = rb0; *(uint4*)&sB[b2][so + 8] = rb1;
            __syncthreads();
            buf = b2;
        }
    }

    float* C = g_sims;
#pragma unroll
    for (int mt = 0; mt < 4; mt++) {
        int r0 = bm + wm + mt * 16 + gid;
#pragma unroll
        for (int nt = 0; nt < 4; nt++) {
            int c0 = bn + wn + nt * 8 + qid * 2;
            float2 v0, v1;
            v0.x = clip10(acc[mt][nt][0] * 5.f);
            v0.y = clip10(acc[mt][nt][1] * 5.f);
            v1.x = clip10(acc[mt][nt][2] * 5.f);
            v1.y = clip10(acc[mt][nt][3] * 5.f);
            *(float2*)&C[(size_t)r0 * MBUF + c0]       = v0;
            *(float2*)&C[(size_t)(r0 + 8) * MBUF + c0] = v1;
        }
    }
}

// ---------------- K3: per-row histogram top-k selection ----------------------
__device__ __forceinline__ int bin_of(float s) {
    int b = (int)(__fmul_rn(__fadd_rn(s, 10.f), 204.8f));  // NBINS/20
    return max(0, min(NBINS - 1, b));
}

__global__ void __launch_bounds__(256) k_select(const int* __restrict__ labels) {
    int row = blockIdx.x, t = threadIdx.x;
    __shared__ unsigned hist[NBINS];
    __shared__ float cand[CAND_MAX];
    __shared__ float rf[256];
    __shared__ int   ri[256];
    __shared__ int   suf[256];
    __shared__ int   sT, sAbove, sNc;

    for (int i = t; i < NBINS; i += 256) hist[i] = 0;
    if (t == 0) sNc = 0;
    unsigned char lab = (unsigned char)labels[row];
    __syncthreads();

    const float* srow = g_sims + (size_t)row * MBUF;

    // Pass A: histogram negatives, accumulate positive exp-sum
    float possum = 0.f; int nneg = 0;
    for (int c = t; c < MBUF; c += 256) {
        float s = srow[c];
        if (g_blu8[c] != lab) {
            nneg++;
            atomicAdd(&hist[bin_of(s)], 1u);
        } else {
            possum += __expf(s);
        }
    }
    rf[t] = possum; ri[t] = nneg; __syncthreads();
    for (int s2 = 128; s2 > 0; s2 >>= 1) {
        if (t < s2) { rf[t] += rf[t + s2]; ri[t] += ri[t + s2]; }
        __syncthreads();
    }
    int n_neg = ri[0]; float pos_sum = rf[0];
    int n_pos = MBUF - n_neg;
    int k = (int)(__fmul_rn(0.7f, (float)n_neg));  // f32 mult + trunc, matches reference
    __syncthreads();

    // suffix scan over bins to find threshold bin T (rank-k from the top)
    const int CH = NBINS / 256;  // 16 bins per thread
    int base = t * CH, cs = 0;
#pragma unroll
    for (int i = 0; i < CH; i++) cs += (int)hist[base + i];
    ri[t] = cs; __syncthreads();
    if (t == 0) {
        int run = 0;
        for (int i = 255; i >= 0; i--) { suf[i] = run; run += ri[i]; }
    }
    __syncthreads();
    if (k > 0) {
        int run = suf[t];
        for (int i = CH - 1; i >= 0; i--) {
            int bb = base + i, c = (int)hist[bb];
            if (run < k && run + c >= k) { sT = bb; sAbove = run; }
            run += c;
        }
    }
    __syncthreads();

    float negexp = 0.f;
    if (k > 0) {
        int T = sT;
        // Pass B: exp-sum above threshold bin; gather threshold-bin candidates
        float hi = 0.f;
        for (int c = t; c < MBUF; c += 256) {
            float s = srow[c];
            if (g_blu8[c] != lab) {
                int bn = bin_of(s);
                if (bn > T) hi += __expf(s);
                else if (bn == T) {
                    int p = atomicAdd(&sNc, 1);
                    if (p < CAND_MAX) cand[p] = s;
                }
            }
        }
        rf[t] = hi; __syncthreads();
        for (int s2 = 128; s2 > 0; s2 >>= 1) {
            if (t < s2) rf[t] += rf[t + s2];
            __syncthreads();
        }
        float sum_hi = rf[0];
        int need = k - sAbove;
        int nc = min(sNc, CAND_MAX);
        __syncthreads();

        float csum = 0.f;
        if (need >= nc) {
            for (int i = t; i < nc; i += 256) csum += __expf(cand[i]);
            if (t == 0 && need > nc) {  // overflow fallback (not expected to trigger)
                float lo = (float)sT * (20.f / NBINS) - 10.f;
                csum += (float)(need - nc) * __expf(lo + 10.f / NBINS);
            }
        } else {
            // exact rank among threshold-bin candidates (tie-break by index; sum-invariant)
            for (int i = t; i < nc; i += 256) {
                float v = cand[i]; int rk = 0;
                for (int j = 0; j < nc; j++) {
                    float u = cand[j];
                    rk += (u > v) || (u == v && j < i);
                }
                if (rk < need) csum += __expf(v);
            }
        }
        rf[t] = csum; __syncthreads();
        for (int s2 = 128; s2 > 0; s2 >>= 1) {
            if (t < s2) rf[t] += rf[t + s2];
            __syncthreads();
        }
        negexp = sum_hi + rf[0];
    }

    if (t == 0) {
        bool valid = (k > 0) && (n_pos > 0);
        float pos_exp = pos_sum / (float)max(n_pos, 1);
        float denom = fmaxf(pos_exp + negexp, 1e-8f);
        float ratio = fminf(fmaxf(pos_exp / denom, 1e-8f), 1.f);
        float loss = fminf(fmaxf(-logf(ratio), 0.f), 5.f);
        g_row_loss[row]  = valid ? loss : 0.f;
        g_row_valid[row] = valid ? 1 : 0;
    }
}

// ---------------- K4: boundary loss per class --------------------------------
__global__ void __launch_bounds__(256) k_boundary(const float* __restrict__ f,
                                                  const int* __restrict__ labels) {
    int c = blockIdx.x, t = threadIdx.x;
    __shared__ float rf[256];
    float s1a = 0, s2a = 0, s1b = 0, s2b = 0, ssum = 0;
    int cnt = 0;
    int d0 = t, d1 = t + 256;
    for (int r = 0; r < BATCH; r++) {
        if (labels[r] == c) {
            float va = f[r * DIM + d0], vb = f[r * DIM + d1];
            s1a += va; s2a += va * va;
            s1b += vb; s2b += vb * vb;
            cnt++;
            if (t == 0) ssum += g_scores[r];
        }
    }
    float n = (float)cnt, safen = fmaxf(n, 1.f), denv = fmaxf(n - 1.f, 1.f);
    float ma = s1a / safen, mb = s1b / safen;
    float va = (s2a - n * ma * ma) / denv, vb = (s2b - n * mb * mb) / denv;
    rf[t] = va + vb; __syncthreads();
    for (int s = 128; s > 0; s >>= 1) {
        if (t < s) rf[t] += rf[t + s];
        __syncthreads();
    }
    if (t == 0) {
        float var_mean = fminf(fmaxf(rf[0] / 512.f, 1e-6f), 100.f);
        float target = 1.f / (1.f + expf(-var_mean));
        float mean_s = ssum / safen;
        float d = mean_s - target;
        float bl = fminf(fmaxf(d * d, 0.f), 2.f);
        g_bl[c] = (cnt > 1) ? bl : 0.f;
        g_vc[c] = (cnt > 1) ? 1 : 0;
    }
}

// ---------------- K5a: normalize selected prototypes (50 old + 50 new) -------
__global__ void k_norm_protos(const float* __restrict__ protos,
                              const float* __restrict__ oldp,
                              const int* __restrict__ lc) {
    int i = blockIdx.x, t = threadIdx.x;
    int j = (i < NLRN) ? i : i - NLRN;
    const float* src = ((i < NLRN) ? oldp : protos) + (size_t)lc[j] * DIM;
    float* dst = ((i < NLRN) ? g_op : g_np) + (size_t)j * DIM;
    __shared__ float r1[128];
    float ss = 0.f;
    for (int d = t; d < DIM; d += 128) { float v = src[d]; ss += v * v; }
    r1[t] = ss; __syncthreads();
    for (int s = 64; s > 0; s >>= 1) {
        if (t < s) r1[t] += r1[t + s];
        __syncthreads();
    }
    float inv = 1.f / fmaxf(sqrtf(r1[0]), 1e-12f);
    for (int d = t; d < DIM; d += 128) dst[d] = src[d] * inv;
}

// ---------------- K5b: PRD KL divergence per row -----------------------------
__global__ void __launch_bounds__(128) k_prd() {
    int row = blockIdx.x, t = threadIdx.x, w = t >> 5, l = t & 31;
    __shared__ float sf[DIM];
    __shared__ float so[NLRN], sn[NLRN];
    for (int d = t; d < DIM; d += 128) sf[d] = g_fn32[(size_t)row * DIM + d];
    __syncthreads();
    for (int j = w; j < NLRN; j += 4) {
        float ao = 0.f, an = 0.f;
        const float* po = g_op + (size_t)j * DIM;
        const float* pn = g_np + (size_t)j * DIM;
        for (int d = l; d < DIM; d += 32) {
            float x = sf[d];
            ao += x * po[d];
            an += x * pn[d];
        }
#pragma unroll
        for (int o = 16; o > 0; o >>= 1) {
            ao += __shfl_down_sync(0xffffffffu, ao, o);
            an += __shfl_down_sync(0xffffffffu, an, o);
        }
        if (l == 0) { so[j] = clip10(ao * 5.f); sn[j] = clip10(an * 5.f); }
    }
    __syncthreads();
    if (w == 0) {
        float a1 = (l < NLRN) ? so[l] : -1e30f;
        float a2 = (l + 32 < NLRN) ? so[l + 32] : -1e30f;
        float b1 = (l < NLRN) ? sn[l] : -1e30f;
        float b2 = (l + 32 < NLRN) ? sn[l + 32] : -1e30f;
        float mo = fmaxf(a1, a2), mn = fmaxf(b1, b2);
#pragma unroll
        for (int o = 16; o > 0; o >>= 1) {
            mo = fmaxf(mo, __shfl_xor_sync(0xffffffffu, mo, o));
            mn = fmaxf(mn, __shfl_xor_sync(0xffffffffu, mn, o));
        }
        float eo = ((l < NLRN) ? __expf(a1 - mo) : 0.f) + ((l + 32 < NLRN) ? __expf(a2 - mo) : 0.f);
        float en = ((l < NLRN) ? __expf(b1 - mn) : 0.f) + ((l + 32 < NLRN) ? __expf(b2 - mn) : 0.f);
#pragma unroll
        for (int o = 16; o > 0; o >>= 1) {
            eo += __shfl_xor_sync(0xffffffffu, eo, o);
            en += __shfl_xor_sync(0xffffffffu, en, o);
        }
        float lZo = logf(eo), lZn = logf(en);
        float klp = 0.f;
        if (l < NLRN) {
            float p = __expf(a1 - mo) / eo;
            klp += p * ((a1 - mo - lZo) - (b1 - mn - lZn));
        }
        if (l + 32 < NLRN) {
            float p = __expf(a2 - mo) / eo;
            klp += p * ((a2 - mo - lZo) - (b2 - mn - lZn));
        }
#pragma unroll
        for (int o = 16; o > 0; o >>= 1) klp += __shfl_xor_sync(0xffffffffu, klp, o);
        if (l == 0) g_row_kl[row] = klp;
    }
}

// ---------------- K6: final deterministic reduction --------------------------
__global__ void k_final(float* __restrict__ out) {
    int t = threadIdx.x;
    __shared__ float rf[256];
    __shared__ int   ri[256];
    float ls = 0.f, kls = 0.f; int vs = 0;
    for (int r = t; r < BATCH; r += 256) {
        ls += g_row_loss[r];
        vs += g_row_valid[r];
        kls += g_row_kl[r];
    }
    float bls = 0.f; int vcs = 0;
    for (int c = t; c < NCLS; c += 256) { bls += g_bl[c]; vcs += g_vc[c]; }

    rf[t] = ls; ri[t] = vs; __syncthreads();
    for (int s = 128; s > 0; s >>= 1) {
        if (t < s) { rf[t] += rf[t + s]; ri[t] += ri[t + s]; }
        __syncthreads();
    }
    float hard = rf[0] / (float)max(ri[0], 1);
    __syncthreads();

    rf[t] = kls; __syncthreads();
    for (int s = 128; s > 0; s >>= 1) {
        if (t < s) rf[t] += rf[t + s];
        __syncthreads();
    }
    float prd = fminf(fmaxf(rf[0] / (float)BATCH, 0.f), 5.f);
    __syncthreads();

    rf[t] = bls; ri[t] = vcs; __syncthreads();
    for (int s = 128; s > 0; s >>= 1) {
        if (t < s) { rf[t] += rf[t + s]; ri[t] += ri[t + s]; }
        __syncthreads();
    }
    if (t == 0) {
        float bnd = rf[0] / (float)max(ri[0], 1);
        out[0] = hard + 0.1f * bnd + 0.2f * prd;
    }
}

// ---------------- entry ------------------------------------------------------
extern "C" void kernel_launch(void* const* d_in, const int* in_sizes, int n_in,
                              void* d_out, int out_size) {
    const float* features        = (const float*)d_in[0];
    const float* buffer_features = (const float*)d_in[1];
    const float* prototypes      = (const float*)d_in[2];
    const float* old_prototypes  = (const float*)d_in[3];
    const float* W               = (const float*)d_in[4];
    const float* b               = (const float*)d_in[5];
    const int*   labels          = (const int*)d_in[6];
    const int*   buffer_labels   = (const int*)d_in[7];
    const int*   learned         = (const int*)d_in[8];

    k_norm_features<<<BATCH, 128>>>(features, W, b);
    k_norm_buffer<<<MBUF, 128>>>(buffer_features, buffer_labels);
    dim3 gg(MBUF / 128, BATCH / 128);
    k_gemm<<<gg, 256>>>();
    k_select<<<BATCH, 256>>>(labels);
    k_boundary<<<NCLS, 256>>>(features, labels);
    k_norm_protos<<<2 * NLRN, 128>>>(prototypes, old_prototypes, learned);
    k_prd<<<BATCH, 128>>>();
    k_final<<<1, 256>>>((float*)d_out);
}

// round 2
// speedup vs baseline: 1.8959x; 1.8959x over previous
#include <cuda_runtime.h>
#include <cuda_bf16.h>
#include <math.h>

#define BATCH 1024
#define MBUF  16384
#define DIM   512
#define NCLS  100
#define NLRN  50
#define NBINS 4096
#define CAND_MAX 4096
#define NCBLK 128            // MBUF/128 column blocks

// ---------------- scratch (__device__ globals; no allocation) ----------------
__device__ __align__(16) __nv_bfloat16 g_fn16[BATCH * DIM];
__device__ __align__(16) float         g_fn32[BATCH * DIM];
__device__ __align__(16) __nv_bfloat16 g_bfn16[(size_t)MBUF * DIM];
__device__ unsigned char               g_blu8[MBUF];
__device__ __align__(16) float         g_scratch[(size_t)BATCH * MBUF]; // fallback only
__device__ float g_pp[BATCH * NCBLK];   // per (row, colblock) positive exp sum
__device__ float g_nn[BATCH * NCBLK];   // per (row, colblock) negative exp sum
__device__ int   g_pc[BATCH * NCBLK];   // per (row, colblock) negative count
__device__ int   g_flag[BATCH];
__device__ float g_scores[BATCH];
__device__ float g_row_loss[BATCH];
__device__ int   g_row_valid[BATCH];
__device__ float g_row_kl[BATCH];
__device__ float g_bl[NCLS];
__device__ int   g_vc[NCLS];
__device__ __align__(16) float g_op[NLRN * DIM];
__device__ __align__(16) float g_np[NLRN * DIM];

__device__ __forceinline__ float clip10(float x) { return fminf(fmaxf(x, -10.f), 10.f); }

// ---------------- K1a: normalize features (warp per row) + scores ------------
__global__ void __launch_bounds__(256) k_norm_features(const float* __restrict__ f,
                                                       const float* __restrict__ W,
                                                       const float* __restrict__ b) {
    int wid = threadIdx.x >> 5, lane = threadIdx.x & 31;
    int r = blockIdx.x * 8 + wid;
    float4 v[4];
    float ss = 0.f, dw = 0.f;
#pragma unroll
    for (int j = 0; j < 4; j++) {
        int d = j * 128 + lane * 4;
        v[j] = *(const float4*)(f + r * DIM + d);
        float4 w4 = *(const float4*)(W + d);
        ss += v[j].x * v[j].x + v[j].y * v[j].y + v[j].z * v[j].z + v[j].w * v[j].w;
        dw += v[j].x * w4.x + v[j].y * w4.y + v[j].z * w4.z + v[j].w * w4.w;
    }
#pragma unroll
    for (int o = 16; o > 0; o >>= 1) {
        ss += __shfl_xor_sync(0xffffffffu, ss, o);
        dw += __shfl_xor_sync(0xffffffffu, dw, o);
    }
    float inv = 1.f / fmaxf(sqrtf(ss), 1e-12f);
    if (lane == 0) g_scores[r] = 1.f / (1.f + expf(-(dw + b[0])));
#pragma unroll
    for (int j = 0; j < 4; j++) {
        int d = j * 128 + lane * 4;
        float4 n;
        n.x = v[j].x * inv; n.y = v[j].y * inv; n.z = v[j].z * inv; n.w = v[j].w * inv;
        *(float4*)(g_fn32 + r * DIM + d) = n;
        __nv_bfloat162* o16 = (__nv_bfloat162*)(g_fn16 + r * DIM + d);
        o16[0] = __floats2bfloat162_rn(n.x, n.y);
        o16[1] = __floats2bfloat162_rn(n.z, n.w);
    }
}

// ---------------- K1b: normalize buffer rows (warp per row) ------------------
__global__ void __launch_bounds__(256) k_norm_buffer(const float* __restrict__ bf,
                                                     const int* __restrict__ blab) {
    int wid = threadIdx.x >> 5, lane = threadIdx.x & 31;
    int r = blockIdx.x * 8 + wid;
    float4 v[4];
    float ss = 0.f;
#pragma unroll
    for (int j = 0; j < 4; j++) {
        int d = j * 128 + lane * 4;
        v[j] = *(const float4*)(bf + (size_t)r * DIM + d);
        ss += v[j].x * v[j].x + v[j].y * v[j].y + v[j].z * v[j].z + v[j].w * v[j].w;
    }
#pragma unroll
    for (int o = 16; o > 0; o >>= 1) ss += __shfl_xor_sync(0xffffffffu, ss, o);
    float inv = 1.f / fmaxf(sqrtf(ss), 1e-12f);
#pragma unroll
    for (int j = 0; j < 4; j++) {
        int d = j * 128 + lane * 4;
        __nv_bfloat162* o16 = (__nv_bfloat162*)(g_bfn16 + (size_t)r * DIM + d);
        o16[0] = __floats2bfloat162_rn(v[j].x * inv, v[j].y * inv);
        o16[1] = __floats2bfloat162_rn(v[j].z * inv, v[j].w * inv);
    }
    if (lane == 0) g_blu8[r] = (unsigned char)blab[r];
}

// ---------------- K2: bf16 MMA GEMM with fused exp/mask row-reduce epilogue --
__global__ void __launch_bounds__(256) k_gemm(const int* __restrict__ labels) {
    __shared__ __nv_bfloat16 sA[2][128 * 40];
    __shared__ __nv_bfloat16 sB[2][128 * 40];
    const __nv_bfloat16* A  = g_fn16;
    const __nv_bfloat16* Bm = g_bfn16;
    int tid  = threadIdx.x;
    int wid  = tid >> 5, lane = tid & 31;
    int gid  = lane >> 2, qid = lane & 3;
    int bm   = blockIdx.y * 128, bn = blockIdx.x * 128;
    int wm   = (wid >> 2) * 64,  wn = (wid & 3) * 32;
    int wnx  = wid & 3;

    float acc[4][4][4];
#pragma unroll
    for (int i = 0; i < 4; i++)
#pragma unroll
        for (int j = 0; j < 4; j++)
#pragma unroll
            for (int q = 0; q < 4; q++) acc[i][j][q] = 0.f;

    int lr = tid >> 1, lc = (tid & 1) * 16;
    const __nv_bfloat16* Ap0 = A  + (size_t)(bm + lr) * DIM + lc;
    const __nv_bfloat16* Bp0 = Bm + (size_t)(bn + lr) * DIM + lc;
    int so = lr * 40 + lc;

    uint4 ra0 = *(const uint4*)Ap0, ra1 = *(const uint4*)(Ap0 + 8);
    uint4 rb0 = *(const uint4*)Bp0, rb1 = *(const uint4*)(Bp0 + 8);
    *(uint4*)&sA[0][so] = ra0; *(uint4*)&sA[0][so + 8] = ra1;
    *(uint4*)&sB[0][so] = rb0; *(uint4*)&sB[0][so + 8] = rb1;
    __syncthreads();

    int buf = 0;
#pragma unroll 1
    for (int kk = 0; kk < 16; kk++) {
        if (kk < 15) {
            const __nv_bfloat16* Ap = Ap0 + (kk + 1) * 32;
            const __nv_bfloat16* Bp = Bp0 + (kk + 1) * 32;
            ra0 = *(const uint4*)Ap; ra1 = *(const uint4*)(Ap + 8);
            rb0 = *(const uint4*)Bp; rb1 = *(const uint4*)(Bp + 8);
        }
        const unsigned* sAu = (const unsigned*)sA[buf];
        const unsigned* sBu = (const unsigned*)sB[buf];
#pragma unroll
        for (int s = 0; s < 2; s++) {
            unsigned afr[4][4], bfr[4][2];
#pragma unroll
            for (int mt = 0; mt < 4; mt++) {
                int rl = (wm + mt * 16 + gid) * 20 + s * 8;
                afr[mt][0] = sAu[rl + qid];
                afr[mt][1] = sAu[rl + 160 + qid];
                afr[mt][2] = sAu[rl + 4 + qid];
                afr[mt][3] = sAu[rl + 164 + qid];
            }
#pragma unroll
            for (int nt = 0; nt < 4; nt++) {
                int rl = (wn + nt * 8 + gid) * 20 + s * 8;
                bfr[nt][0] = sBu[rl + qid];
                bfr[nt][1] = sBu[rl + 4 + qid];
            }
#pragma unroll
            for (int mt = 0; mt < 4; mt++)
#pragma unroll
                for (int nt = 0; nt < 4; nt++) {
                    asm volatile(
                        "mma.sync.aligned.m16n8k16.row.col.f32.bf16.bf16.f32 "
                        "{%0,%1,%2,%3}, {%4,%5,%6,%7}, {%8,%9}, {%0,%1,%2,%3};\n"
                        : "+f"(acc[mt][nt][0]), "+f"(acc[mt][nt][1]),
                          "+f"(acc[mt][nt][2]), "+f"(acc[mt][nt][3])
                        : "r"(afr[mt][0]), "r"(afr[mt][1]), "r"(afr[mt][2]), "r"(afr[mt][3]),
                          "r"(bfr[nt][0]), "r"(bfr[nt][1]));
                }
        }
        if (kk < 15) {
            int b2 = buf ^ 1;
            *(uint4*)&sA[b2][so] = ra0; *(uint4*)&sA[b2][so + 8] = ra1;
            *(uint4*)&sB[b2][so] = rb0; *(uint4*)&sB[b2][so + 8] = rb1;
            __syncthreads();
            buf = b2;
        }
    }

    // ---- epilogue: per-row (pos_exp_sum, neg_exp_sum, neg_count) over this
    //      128-col block. Deterministic: fixed lane order + fixed slot sums.
    __syncthreads();
    float* s_pp = (float*)&sA[0][0];          // [128][4]
    float* s_nn = s_pp + 512;                 // [128][4]
    int*   s_nc = (int*)(s_nn + 512);         // [128][4]

#pragma unroll
    for (int mt = 0; mt < 4; mt++) {
#pragma unroll
        for (int h = 0; h < 2; h++) {
            int rl = wm + mt * 16 + gid + h * 8;
            unsigned char rowlab = (unsigned char)labels[bm + rl];
            float pos = 0.f, neg = 0.f;
            int nneg = 0;
#pragma unroll
            for (int nt = 0; nt < 4; nt++) {
#pragma unroll
                for (int cc = 0; cc < 2; cc++) {
                    int cl = wn + nt * 8 + qid * 2 + cc;
                    float v = clip10(acc[mt][nt][h * 2 + cc] * 5.f);
                    float e = __expf(v);
                    if (g_blu8[bn + cl] != rowlab) { neg += e; nneg++; }
                    else pos += e;
                }
            }
            pos += __shfl_xor_sync(0xffffffffu, pos, 1);
            pos += __shfl_xor_sync(0xffffffffu, pos, 2);
            neg += __shfl_xor_sync(0xffffffffu, neg, 1);
            neg += __shfl_xor_sync(0xffffffffu, neg, 2);
            nneg += __shfl_xor_sync(0xffffffffu, nneg, 1);
            nneg += __shfl_xor_sync(0xffffffffu, nneg, 2);
            if (qid == 0) {
                s_pp[rl * 4 + wnx] = pos;
                s_nn[rl * 4 + wnx] = neg;
                s_nc[rl * 4 + wnx] = nneg;
            }
        }
    }
    __syncthreads();
    if (tid < 128) {
        float pp = s_pp[tid * 4] + s_pp[tid * 4 + 1] + s_pp[tid * 4 + 2] + s_pp[tid * 4 + 3];
        float nn = s_nn[tid * 4] + s_nn[tid * 4 + 1] + s_nn[tid * 4 + 2] + s_nn[tid * 4 + 3];
        int   nc = s_nc[tid * 4] + s_nc[tid * 4 + 1] + s_nc[tid * 4 + 2] + s_nc[tid * 4 + 3];
        int row = bm + tid;
        g_pp[row * NCBLK + blockIdx.x] = pp;
        g_nn[row * NCBLK + blockIdx.x] = nn;
        g_pc[row * NCBLK + blockIdx.x] = nc;
    }
}

// ---------------- K3a: reduce partials, provable-clip fast path --------------
__global__ void __launch_bounds__(128) k_rowstats() {
    int row = blockIdx.x, t = threadIdx.x;
    __shared__ float ap[128], an[128];
    __shared__ int ac[128];
    ap[t] = g_pp[row * NCBLK + t];
    an[t] = g_nn[row * NCBLK + t];
    ac[t] = g_pc[row * NCBLK + t];
    __syncthreads();
    for (int s = 64; s > 0; s >>= 1) {
        if (t < s) { ap[t] += ap[t + s]; an[t] += an[t + s]; ac[t] += ac[t + s]; }
        __syncthreads();
    }
    if (t == 0) {
        float pos_sum = ap[0], neg_sum = an[0];
        int n_neg = ac[0];
        int n_pos = MBUF - n_neg;
        int k = (int)(__fmul_rn(0.7f, (float)n_neg));
        bool valid = (k > 0) && (n_pos > 0);
        if (!valid) {
            g_row_loss[row] = 0.f; g_row_valid[row] = 0; g_flag[row] = 0;
        } else {
            float pos_exp = pos_sum / (float)max(n_pos, 1);
            // top-k sum >= (k/n_neg) * total_neg_sum; loss clips to 5 iff
            // neg_topk >= (e^5-1)*pos_exp ~= 147.4*pos_exp. Use 600x margin.
            float bound = neg_sum * ((float)k / (float)n_neg);
            if (bound >= 600.f * pos_exp) {
                g_row_loss[row] = 5.f; g_row_valid[row] = 1; g_flag[row] = 0;
            } else {
                g_flag[row] = 1;   // exact kernel fills loss/valid
            }
        }
    }
}

// ---------------- K3b: exact fallback (rarely/never runs; early exit) --------
__device__ __forceinline__ int bin_of(float s) {
    int b = (int)(__fmul_rn(__fadd_rn(s, 10.f), 204.8f));
    return max(0, min(NBINS - 1, b));
}

__global__ void __launch_bounds__(256) k_select_exact(const int* __restrict__ labels) {
    int row = blockIdx.x, t = threadIdx.x;
    if (!g_flag[row]) return;

    __shared__ float sf[DIM];
    __shared__ unsigned hist[NBINS];
    __shared__ float cand[CAND_MAX];
    __shared__ float rf[256];
    __shared__ int   ri[256];
    __shared__ int   suf[256];
    __shared__ int   sT, sAbove, sNc;

    for (int d = t; d < DIM; d += 256) sf[d] = g_fn32[(size_t)row * DIM + d];
    for (int i = t; i < NBINS; i += 256) hist[i] = 0;
    if (t == 0) sNc = 0;
    unsigned char lab = (unsigned char)labels[row];
    __syncthreads();

    float* srow = g_scratch + (size_t)row * MBUF;
    for (int c = t; c < MBUF; c += 256) {
        const __nv_bfloat16* bp = g_bfn16 + (size_t)c * DIM;
        float dot = 0.f;
        for (int d = 0; d < DIM; d++) dot += sf[d] * __bfloat162float(bp[d]);
        srow[c] = clip10(dot * 5.f);
    }
    __syncthreads();

    float possum = 0.f; int nneg = 0;
    for (int c = t; c < MBUF; c += 256) {
        float s = srow[c];
        if (g_blu8[c] != lab) { nneg++; atomicAdd(&hist[bin_of(s)], 1u); }
        else possum += __expf(s);
    }
    rf[t] = possum; ri[t] = nneg; __syncthreads();
    for (int s2 = 128; s2 > 0; s2 >>= 1) {
        if (t < s2) { rf[t] += rf[t + s2]; ri[t] += ri[t + s2]; }
        __syncthreads();
    }
    int n_neg = ri[0]; float pos_sum = rf[0];
    int n_pos = MBUF - n_neg;
    int k = (int)(__fmul_rn(0.7f, (float)n_neg));
    __syncthreads();

    const int CH = NBINS / 256;
    int base = t * CH, cs = 0;
#pragma unroll
    for (int i = 0; i < CH; i++) cs += (int)hist[base + i];
    ri[t] = cs; __syncthreads();
    if (t == 0) {
        int run = 0;
        for (int i = 255; i >= 0; i--) { suf[i] = run; run += ri[i]; }
    }
    __syncthreads();
    if (k > 0) {
        int run = suf[t];
        for (int i = CH - 1; i >= 0; i--) {
            int bb = base + i, c = (int)hist[bb];
            if (run < k && run + c >= k) { sT = bb; sAbove = run; }
            run += c;
        }
    }
    __syncthreads();

    float negexp = 0.f;
    if (k > 0) {
        int T = sT;
        float hi = 0.f;
        for (int c = t; c < MBUF; c += 256) {
            float s = srow[c];
            if (g_blu8[c] != lab) {
                int bn = bin_of(s);
                if (bn > T) hi += __expf(s);
                else if (bn == T) {
                    int p = atomicAdd(&sNc, 1);
                    if (p < CAND_MAX) cand[p] = s;
                }
            }
        }
        rf[t] = hi; __syncthreads();
        for (int s2 = 128; s2 > 0; s2 >>= 1) {
            if (t < s2) rf[t] += rf[t + s2];
            __syncthreads();
        }
        float sum_hi = rf[0];
        int need = k - sAbove;
        int nc = min(sNc, CAND_MAX);
        __syncthreads();

        float csum = 0.f;
        if (need >= nc) {
            for (int i = t; i < nc; i += 256) csum += __expf(cand[i]);
            if (t == 0 && need > nc) {
                float lo = (float)sT * (20.f / NBINS) - 10.f;
                csum += (float)(need - nc) * __expf(lo + 10.f / NBINS);
            }
        } else {
            for (int i = t; i < nc; i += 256) {
                float v = cand[i]; int rk = 0;
                for (int j = 0; j < nc; j++) {
                    float u = cand[j];
                    rk += (u > v) || (u == v && j < i);
                }
                if (rk < need) csum += __expf(v);
            }
        }
        rf[t] = csum; __syncthreads();
        for (int s2 = 128; s2 > 0; s2 >>= 1) {
            if (t < s2) rf[t] += rf[t + s2];
            __syncthreads();
        }
        negexp = sum_hi + rf[0];
    }

    if (t == 0) {
        bool valid = (k > 0) && (n_pos > 0);
        float pos_exp = pos_sum / (float)max(n_pos, 1);
        float denom = fmaxf(pos_exp + negexp, 1e-8f);
        float ratio = fminf(fmaxf(pos_exp / denom, 1e-8f), 1.f);
        float loss = fminf(fmaxf(-logf(ratio), 0.f), 5.f);
        g_row_loss[row]  = valid ? loss : 0.f;
        g_row_valid[row] = valid ? 1 : 0;
    }
}

// ---------------- K4: boundary loss per class --------------------------------
__global__ void __launch_bounds__(256) k_boundary(const float* __restrict__ f,
                                                  const int* __restrict__ labels) {
    int c = blockIdx.x, t = threadIdx.x;
    __shared__ float rf[256];
    float s1a = 0, s2a = 0, s1b = 0, s2b = 0, ssum = 0;
    int cnt = 0;
    int d0 = t, d1 = t + 256;
    for (int r = 0; r < BATCH; r++) {
        if (labels[r] == c) {
            float va = f[r * DIM + d0], vb = f[r * DIM + d1];
            s1a += va; s2a += va * va;
            s1b += vb; s2b += vb * vb;
            cnt++;
            if (t == 0) ssum += g_scores[r];
        }
    }
    float n = (float)cnt, safen = fmaxf(n, 1.f), denv = fmaxf(n - 1.f, 1.f);
    float ma = s1a / safen, mb = s1b / safen;
    float va = (s2a - n * ma * ma) / denv, vb = (s2b - n * mb * mb) / denv;
    rf[t] = va + vb; __syncthreads();
    for (int s = 128; s > 0; s >>= 1) {
        if (t < s) rf[t] += rf[t + s];
        __syncthreads();
    }
    if (t == 0) {
        float var_mean = fminf(fmaxf(rf[0] / 512.f, 1e-6f), 100.f);
        float target = 1.f / (1.f + expf(-var_mean));
        float mean_s = ssum / safen;
        float d = mean_s - target;
        float bl = fminf(fmaxf(d * d, 0.f), 2.f);
        g_bl[c] = (cnt > 1) ? bl : 0.f;
        g_vc[c] = (cnt > 1) ? 1 : 0;
    }
}

// ---------------- K5a: normalize selected prototypes -------------------------
__global__ void k_norm_protos(const float* __restrict__ protos,
                              const float* __restrict__ oldp,
                              const int* __restrict__ lc) {
    int i = blockIdx.x, t = threadIdx.x;
    int j = (i < NLRN) ? i : i - NLRN;
    const float* src = ((i < NLRN) ? oldp : protos) + (size_t)lc[j] * DIM;
    float* dst = ((i < NLRN) ? g_op : g_np) + (size_t)j * DIM;
    __shared__ float r1[128];
    float ss = 0.f;
    for (int d = t; d < DIM; d += 128) { float v = src[d]; ss += v * v; }
    r1[t] = ss; __syncthreads();
    for (int s = 64; s > 0; s >>= 1) {
        if (t < s) r1[t] += r1[t + s];
        __syncthreads();
    }
    float inv = 1.f / fmaxf(sqrtf(r1[0]), 1e-12f);
    for (int d = t; d < DIM; d += 128) dst[d] = src[d] * inv;
}

// ---------------- K5b: PRD KL divergence (8 rows per block) ------------------
__global__ void __launch_bounds__(256) k_prd() {
    int t = threadIdx.x, w = t >> 5, l = t & 31;
    int base = blockIdx.x * 8;
    __shared__ float sf[8][DIM];          // 16 KB
    __shared__ float so[8][64], sn[8][64];
    for (int i = t; i < 8 * DIM / 4; i += 256) {
        ((float4*)&sf[0][0])[i] = ((const float4*)(g_fn32 + (size_t)base * DIM))[i];
    }
    __syncthreads();
    for (int j = w; j < NLRN; j += 8) {
        float po_r[16], pn_r[16];
#pragma unroll
        for (int q = 0; q < 16; q++) {
            po_r[q] = g_op[j * DIM + l + 32 * q];
            pn_r[q] = g_np[j * DIM + l + 32 * q];
        }
#pragma unroll
        for (int r = 0; r < 8; r++) {
            float ao = 0.f, an = 0.f;
#pragma unroll
            for (int q = 0; q < 16; q++) {
                float x = sf[r][l + 32 * q];
                ao += x * po_r[q];
                an += x * pn_r[q];
            }
#pragma unroll
            for (int o = 16; o > 0; o >>= 1) {
                ao += __shfl_xor_sync(0xffffffffu, ao, o);
                an += __shfl_xor_sync(0xffffffffu, an, o);
            }
            if (l == 0) { so[r][j] = clip10(ao * 5.f); sn[r][j] = clip10(an * 5.f); }
        }
    }
    __syncthreads();
    {
        int r = w;   // warp w handles row base+w
        float a1 = (l < NLRN) ? so[r][l] : -1e30f;
        float a2 = (l + 32 < NLRN) ? so[r][l + 32] : -1e30f;
        float b1 = (l < NLRN) ? sn[r][l] : -1e30f;
        float b2 = (l + 32 < NLRN) ? sn[r][l + 32] : -1e30f;
        float mo = fmaxf(a1, a2), mn = fmaxf(b1, b2);
#pragma unroll
        for (int o = 16; o > 0; o >>= 1) {
            mo = fmaxf(mo, __shfl_xor_sync(0xffffffffu, mo, o));
            mn = fmaxf(mn, __shfl_xor_sync(0xffffffffu, mn, o));
        }
        float eo = ((l < NLRN) ? __expf(a1 - mo) : 0.f) + ((l + 32 < NLRN) ? __expf(a2 - mo) : 0.f);
        float en = ((l < NLRN) ? __expf(b1 - mn) : 0.f) + ((l + 32 < NLRN) ? __expf(b2 - mn) : 0.f);
#pragma unroll
        for (int o = 16; o > 0; o >>= 1) {
            eo += __shfl_xor_sync(0xffffffffu, eo, o);
            en += __shfl_xor_sync(0xffffffffu, en, o);
        }
        float lZo = logf(eo), lZn = logf(en);
        float klp = 0.f;
        if (l < NLRN) {
            float p = __expf(a1 - mo) / eo;
            klp += p * ((a1 - mo - lZo) - (b1 - mn - lZn));
        }
        if (l + 32 < NLRN) {
            float p = __expf(a2 - mo) / eo;
            klp += p * ((a2 - mo - lZo) - (b2 - mn - lZn));
        }
#pragma unroll
        for (int o = 16; o > 0; o >>= 1) klp += __shfl_xor_sync(0xffffffffu, klp, o);
        if (l == 0) g_row_kl[base + r] = klp;
    }
}

// ---------------- K6: final deterministic reduction --------------------------
__global__ void k_final(float* __restrict__ out) {
    int t = threadIdx.x;
    __shared__ float rf[256];
    __shared__ int   ri[256];
    float ls = 0.f, kls = 0.f; int vs = 0;
    for (int r = t; r < BATCH; r += 256) {
        ls += g_row_loss[r];
        vs += g_row_valid[r];
        kls += g_row_kl[r];
    }
    float bls = 0.f; int vcs = 0;
    for (int c = t; c < NCLS; c += 256) { bls += g_bl[c]; vcs += g_vc[c]; }

    rf[t] = ls; ri[t] = vs; __syncthreads();
    for (int s = 128; s > 0; s >>= 1) {
        if (t < s) { rf[t] += rf[t + s]; ri[t] += ri[t + s]; }
        __syncthreads();
    }
    float hard = rf[0] / (float)max(ri[0], 1);
    __syncthreads();

    rf[t] = kls; __syncthreads();
    for (int s = 128; s > 0; s >>= 1) {
        if (t < s) rf[t] += rf[t + s];
        __syncthreads();
    }
    float prd = fminf(fmaxf(rf[0] / (float)BATCH, 0.f), 5.f);
    __syncthreads();

    rf[t] = bls; ri[t] = vcs; __syncthreads();
    for (int s = 128; s > 0; s >>= 1) {
        if (t < s) { rf[t] += rf[t + s]; ri[t] += ri[t + s]; }
        __syncthreads();
    }
    if (t == 0) {
        float bnd = rf[0] / (float)max(ri[0], 1);
        out[0] = hard + 0.1f * bnd + 0.2f * prd;
    }
}

// ---------------- entry ------------------------------------------------------
extern "C" void kernel_launch(void* const* d_in, const int* in_sizes, int n_in,
                              void* d_out, int out_size) {
    const float* features        = (const float*)d_in[0];
    const float* buffer_features = (const float*)d_in[1];
    const float* prototypes      = (const float*)d_in[2];
    const float* old_prototypes  = (const float*)d_in[3];
    const float* W               = (const float*)d_in[4];
    const float* b               = (const float*)d_in[5];
    const int*   labels          = (const int*)d_in[6];
    const int*   buffer_labels   = (const int*)d_in[7];
    const int*   learned         = (const int*)d_in[8];

    k_norm_features<<<BATCH / 8, 256>>>(features, W, b);
    k_norm_buffer<<<MBUF / 8, 256>>>(buffer_features, buffer_labels);
    dim3 gg(MBUF / 128, BATCH / 128);
    k_gemm<<<gg, 256>>>(labels);
    k_rowstats<<<BATCH, 128>>>();
    k_select_exact<<<BATCH, 256>>>(labels);
    k_boundary<<<NCLS, 256>>>(features, labels);
    k_norm_protos<<<2 * NLRN, 128>>>(prototypes, old_prototypes, learned);
    k_prd<<<BATCH / 8, 256>>>();
    k_final<<<1, 256>>>((float*)d_out);
}